// round 4
// baseline (speedup 1.0000x reference)
#include <cuda_runtime.h>
#include <cstdint>

#define Bv 128
#define Nv 512
#define Xv 128
#define Hv 256
#define BN (Bv*Nv)           // 65536
#define GSZ (BN*Hv)          // 16777216 floats per gate buffer

// 6 precomputed gate-input buffers: 0=fg_x 1=ig_x 2=in_x 3=og_x 4=tm1 5=tm2
__device__ float g_pre[6][GSZ];

__device__ __forceinline__ float sigmoidf_(float v) { return 1.0f / (1.0f + __expf(-v)); }

__device__ __forceinline__ uint32_t smem_u32_(const void* p) {
    uint32_t a;
    asm("{ .reg .u64 t; cvta.to.shared.u64 t, %1; cvt.u32.u64 %0, t; }" : "=r"(a) : "l"(p));
    return a;
}

// ---- f32x2 packed-math helpers (sm_100a) ----
__device__ __forceinline__ unsigned long long pack2_(float a) {
    unsigned long long r;
    asm("mov.b64 %0, {%1, %1};" : "=l"(r) : "f"(a));
    return r;
}
__device__ __forceinline__ void ffma2_(unsigned long long& d, unsigned long long a, unsigned long long b) {
    asm("fma.rn.f32x2 %0, %1, %2, %0;" : "+l"(d) : "l"(a), "l"(b));
}
__device__ __forceinline__ float2 unpack2_(unsigned long long v) {
    float lo, hi;
    asm("mov.b64 {%0, %1}, %2;" : "=f"(lo), "=f"(hi) : "l"(v));
    return make_float2(lo, hi);
}

// Remote (DSMEM) store with mbarrier complete_tx: pushes 4 bytes into rank's
// buffer and credits that rank's mbarrier transaction count.
__device__ __forceinline__ void st_async_f32(uint32_t daddr, uint32_t mbaddr,
                                             uint32_t rank, float v) {
    asm volatile(
        "{\n\t"
        ".reg .b32 ra, rm;\n\t"
        "mapa.shared::cluster.u32 ra, %0, %2;\n\t"
        "mapa.shared::cluster.u32 rm, %1, %2;\n\t"
        "st.async.shared::cluster.mbarrier::complete_tx::bytes.b32 [ra], %3, [rm];\n\t"
        "}"
        :: "r"(daddr), "r"(mbaddr), "r"(rank), "r"(__float_as_uint(v)) : "memory");
}

#define MBAR_INIT_(a, c) \
    asm volatile("mbarrier.init.shared.b64 [%0], %1;" :: "r"(a), "r"(c) : "memory")

#define MBAR_ARRIVE_EXPECT_(a, bytes) \
    asm volatile("mbarrier.arrive.expect_tx.shared.b64 _, [%0], %1;" \
                 :: "r"(a), "r"(bytes) : "memory")

__device__ __forceinline__ void mbar_wait_(uint32_t a, uint32_t parity) {
    asm volatile(
        "{\n\t"
        ".reg .pred P;\n\t"
        "WL_%=:\n\t"
        "mbarrier.try_wait.parity.acquire.cta.shared::cta.b64 P, [%0], %1, 0x989680;\n\t"
        "@P bra.uni WD_%=;\n\t"
        "bra.uni WL_%=;\n\t"
        "WD_%=:\n\t"
        "}"
        :: "r"(a), "r"(parity) : "memory");
}

#define CLUSTER_SYNC_() do { \
    asm volatile("barrier.cluster.arrive.aligned;" ::: "memory"); \
    asm volatile("barrier.cluster.wait.aligned;"   ::: "memory"); \
} while (0)

// ============================================================================
// Phase 1: precompute all input-dependent gate terms.
// grid (512 bn-tiles, 12 h-tiles), block 256, dyn smem 133120 B.
// ============================================================================

#define PC_STEP2(CC, COMP)                                                     \
    {                                                                          \
        const float* wr = ws + (k4 * 4 + CC) * 132 + tcol * 8;                 \
        ulonglong2 b01 = *(const ulonglong2*)(wr);                             \
        ulonglong2 b23 = *(const ulonglong2*)(wr + 4);                         \
        _Pragma("unroll")                                                      \
        for (int i = 0; i < 8; i++) {                                          \
            unsigned long long aa = pack2_(av[i].COMP);                        \
            ffma2_(acc2[i][0], aa, b01.x);                                     \
            ffma2_(acc2[i][1], aa, b01.y);                                     \
            ffma2_(acc2[i][2], aa, b23.x);                                     \
            ffma2_(acc2[i][3], aa, b23.y);                                     \
        }                                                                      \
    }

__global__ void __launch_bounds__(256, 1) precompute_kernel(
    const float* __restrict__ x, const float* __restrict__ tvec,
    const float* __restrict__ fg_w_x, const float* __restrict__ fg_b,
    const float* __restrict__ ig_w_x, const float* __restrict__ ig_b,
    const float* __restrict__ in_w_x, const float* __restrict__ in_b,
    const float* __restrict__ og_w_x, const float* __restrict__ og_b, const float* __restrict__ og_w_t,
    const float* __restrict__ tg1_w_x, const float* __restrict__ tg1_b, const float* __restrict__ tg1_w_t,
    const float* __restrict__ tg2_w_x, const float* __restrict__ tg2_b, const float* __restrict__ tg2_w_t)
{
    extern __shared__ float sm[];
    float* xs = sm;               // [128][128]
    float* ws = sm + 128 * 128;   // [128][132]  (transposed weights, padded)

    const int tid  = threadIdx.x;
    const int bn0  = blockIdx.x * 128;
    const int ht   = blockIdx.y;
    const int gate = ht >> 1;
    const int hl0  = (ht & 1) * 128;

    const float* wptr; const float* bptr; const float* tptr = nullptr;
    switch (gate) {
        case 0:  wptr = fg_w_x;  bptr = fg_b;  break;
        case 1:  wptr = ig_w_x;  bptr = ig_b;  break;
        case 2:  wptr = in_w_x;  bptr = in_b;  break;
        case 3:  wptr = og_w_x;  bptr = og_b;  tptr = og_w_t;  break;
        case 4:  wptr = tg1_w_x; bptr = tg1_b; tptr = tg1_w_t; break;
        default: wptr = tg2_w_x; bptr = tg2_b; tptr = tg2_w_t; break;
    }

    for (int i = tid; i < 4096; i += 256) {
        int row = i >> 5, kq = i & 31;
        *(float4*)(xs + row * 128 + kq * 4) =
            *(const float4*)(x + (size_t)(bn0 + row) * 128 + kq * 4);
    }
    for (int i = tid; i < 4096; i += 256) {
        int h = i >> 5, kq = i & 31;
        float4 v = *(const float4*)(wptr + (size_t)(hl0 + h) * 128 + kq * 4);
        ws[(kq * 4 + 0) * 132 + h] = v.x;
        ws[(kq * 4 + 1) * 132 + h] = v.y;
        ws[(kq * 4 + 2) * 132 + h] = v.z;
        ws[(kq * 4 + 3) * 132 + h] = v.w;
    }
    __syncthreads();

    const int trow = tid >> 4;   // 0..15
    const int tcol = tid & 15;   // 0..15

    unsigned long long acc2[8][4];
    #pragma unroll
    for (int i = 0; i < 8; i++) {
        #pragma unroll
        for (int q = 0; q < 4; q++) acc2[i][q] = 0ull;
    }

    #pragma unroll 2
    for (int k4 = 0; k4 < 32; ++k4) {
        float4 av[8];
        #pragma unroll
        for (int i = 0; i < 8; i++)
            av[i] = *(const float4*)(xs + (trow * 8 + i) * 128 + k4 * 4);
        PC_STEP2(0, x)
        PC_STEP2(1, y)
        PC_STEP2(2, z)
        PC_STEP2(3, w)
    }

    const int hgbase = hl0 + tcol * 8;
    float bias[8], tw[8];
    #pragma unroll
    for (int jj = 0; jj < 8; jj++) {
        bias[jj] = bptr[hgbase + jj];
        tw[jj]   = (tptr != nullptr) ? tptr[hgbase + jj] : 0.0f;
    }
    float* outg = &g_pre[gate][0];
    #pragma unroll
    for (int i = 0; i < 8; i++) {
        int row = bn0 + trow * 8 + i;
        float tv = (gate >= 3) ? tvec[row] : 0.0f;
        float oo[8];
        #pragma unroll
        for (int q = 0; q < 4; q++) {
            float2 u = unpack2_(acc2[i][q]);
            oo[2 * q]     = u.x;
            oo[2 * q + 1] = u.y;
        }
        float o[8];
        #pragma unroll
        for (int jj = 0; jj < 8; jj++) {
            float v;
            if (gate < 3)       v = oo[jj] + bias[jj];
            else if (gate == 3) v = oo[jj] + tw[jj] * tv + bias[jj];
            else                v = sigmoidf_(oo[jj] + tanhf(tw[jj] * tv) + bias[jj]);
            o[jj] = v;
        }
        float4* dst = (float4*)(outg + (size_t)row * 256 + hgbase);
        dst[0] = make_float4(o[0], o[1], o[2], o[3]);
        dst[1] = make_float4(o[4], o[5], o[6], o[7]);
    }
}

// ============================================================================
// Phase 2: recurrence. 16 clusters of 8 CTAs, 512 threads/CTA (16 warps).
// Cluster c: batch rows [8c, 8c+8). Rank r: H-slice [32r, 32r+32).
// Weights (4 g x 32 j x 256 k fp32, f32x2-paired) SMEM-resident.
// Per step: 16-way k-split matmul -> smem reduction -> gates (warps 0-7) ->
// st.async push of new h to all 8 ranks' next-parity buffer + mbarrier
// complete_tx (8192 B/step). expect_tx for step n+1 is posted at the END of
// step n (same phase), so the consumer wait at step n+1 only needs the last
// complete_tx (60-cyc wakeup path). No cluster.sync in the loop.
// ============================================================================

#define REC_THREADS 512
#define HB_OFF   32768
#define RED_OFF  36864
#define MB_OFF   53248   // float index of mbar area (16 floats = 64 B)
#define SMEM_REC_BYTES ((MB_OFF + 16) * 4)

__global__ void __cluster_dims__(8, 1, 1) __launch_bounds__(REC_THREADS, 1) lstm_rec_kernel(
    const float* __restrict__ fg_w_c, const float* __restrict__ fg_w_h,
    const float* __restrict__ ig_w_c, const float* __restrict__ ig_w_h,
    const float* __restrict__ in_w_h,
    const float* __restrict__ og_w_cn, const float* __restrict__ og_w_h,
    float* __restrict__ out)
{
    extern __shared__ float sm[];
    float* Wt4  = sm;               // paired: [k2 128][gp 2][j 32][gl 2][p 2]
    float* hbuf = sm + HB_OFF;      // [2 parity][8 b][256 h]
    float2* red2 = (float2*)(sm + RED_OFF);  // [kc 16][gp 2][bb 8][j 32] float2

    const int tid = threadIdx.x;
    const int r   = blockIdx.x & 7;
    const int grp = blockIdx.x >> 3;
    const int j   = tid & 31;          // output column within slice
    const int kb  = tid >> 5;          // warp id = k-chunk (16 k each)
    const int jg  = r * 32 + j;
    const int bg  = grp * 8 + kb;      // valid for kb<8 (epilogue role)

    const uint32_t sbase = smem_u32_(sm);
    const uint32_t mb0 = sbase + MB_OFF * 4;
    const uint32_t mb1 = mb0 + 8;

    // Paired weight fill: Wt4[k2*256 + gp*128 + j*4 + gl*2 + p] = W_g[r*32+j][2*k2+p]
    for (int idx = tid; idx < 32768; idx += REC_THREADS) {
        int p  = idx & 1;
        int gl = (idx >> 1) & 1;
        int jj = (idx >> 2) & 31;
        int gp = (idx >> 7) & 1;
        int k2 = idx >> 8;
        int g  = gp * 2 + gl;
        const float* W = (g == 0) ? ig_w_h : (g == 1) ? fg_w_h
                       : (g == 2) ? in_w_h : og_w_h;
        Wt4[idx] = W[(size_t)(r * 32 + jj) * 256 + (2 * k2 + p)];
    }
    for (int idx = tid; idx < 4096; idx += REC_THREADS) hbuf[idx] = 0.0f;

    if (tid == 0) {
        MBAR_INIT_(mb0, 1);
        MBAR_INIT_(mb1, 1);
    }

    const float wc_ig = ig_w_c[jg];
    const float wc_fg = fg_w_c[jg];
    const float wc_og = og_w_cn[jg];

    __syncthreads();
    CLUSTER_SYNC_();   // peers' mbarriers + zeroed buffers ready before any st.async

    float cm = 0.0f, hn = 0.0f;
    uint32_t ph0 = 0, ph1 = 0;
    const size_t rowoff = (size_t)bg * Nv * 256 + jg;

    #pragma unroll 1
    for (int n = 0; n < Nv; ++n) {
        const int q = n & 1;
        if (n != 0) {
            mbar_wait_(q ? mb1 : mb0, q ? ph1 : ph0);
            if (q) ph1 ^= 1; else ph0 ^= 1;
        }

        // Prefetch streamed gate terms (owners only)
        float p_fg = 0.f, p_ig = 0.f, p_in = 0.f, p_og = 0.f, p_t1 = 0.f, p_t2 = 0.f;
        if (kb < 8) {
            const size_t off = rowoff + (size_t)n * 256;
            p_fg = __ldcs(&g_pre[0][off]);
            p_ig = __ldcs(&g_pre[1][off]);
            p_in = __ldcs(&g_pre[2][off]);
            p_og = __ldcs(&g_pre[3][off]);
            p_t1 = __ldcs(&g_pre[4][off]);
            p_t2 = __ldcs(&g_pre[5][off]);
        }

        // Partial matmul: warp kb covers k in [16*kb, 16*kb+16), col j,
        // 8 batch rows, 4 gates. f32x2 pairs along k.
        unsigned long long aig[8], afg[8], ain[8], aog[8];
        #pragma unroll
        for (int qq = 0; qq < 8; qq++) { aig[qq] = 0ull; afg[qq] = 0ull; ain[qq] = 0ull; aog[qq] = 0ull; }

        {
            const float* hc = hbuf + q * 2048 + kb * 16;
            const float* wb = Wt4 + (kb * 8) * 256 + j * 4;
            #pragma unroll
            for (int k2 = 0; k2 < 8; ++k2) {
                unsigned long long hv[8];
                #pragma unroll
                for (int bb = 0; bb < 8; bb++)
                    hv[bb] = *(const unsigned long long*)(hc + bb * 256 + 2 * k2);
                const float* wp = wb + k2 * 256;
                ulonglong2 wA = *(const ulonglong2*)(wp);        // (ig pair, fg pair)
                ulonglong2 wB = *(const ulonglong2*)(wp + 128);  // (in pair, og pair)
                #pragma unroll
                for (int bb = 0; bb < 8; bb++) {
                    ffma2_(aig[bb], wA.x, hv[bb]);
                    ffma2_(afg[bb], wA.y, hv[bb]);
                    ffma2_(ain[bb], wB.x, hv[bb]);
                    ffma2_(aog[bb], wB.y, hv[bb]);
                }
            }
        }

        // Stash partials as float2 (ig,fg) and (in,og): red2[kc][gp][bb][j]
        {
            #pragma unroll
            for (int bb = 0; bb < 8; bb++) {
                float2 uig = unpack2_(aig[bb]);
                float2 ufg = unpack2_(afg[bb]);
                float2 uin = unpack2_(ain[bb]);
                float2 uog = unpack2_(aog[bb]);
                red2[((kb * 16) + bb) * 32 + j]     = make_float2(uig.x + uig.y, ufg.x + ufg.y);
                red2[((kb * 16) + 8 + bb) * 32 + j] = make_float2(uin.x + uin.y, uog.x + uog.y);
            }
        }
        __syncthreads();

        if (kb < 8) {
            float s_ig = 0.f, s_fg = 0.f, s_in = 0.f, s_og = 0.f;
            #pragma unroll
            for (int kc = 0; kc < 16; kc++) {
                float2 v01 = red2[((kc * 16) + kb) * 32 + j];
                float2 v23 = red2[((kc * 16) + 8 + kb) * 32 + j];
                s_ig += v01.x; s_fg += v01.y; s_in += v23.x; s_og += v23.y;
            }

            float ig  = sigmoidf_(wc_ig * cm + s_ig + p_ig);
            float fg  = sigmoidf_(wc_fg * cm + s_fg + p_fg);
            float inn = tanhf(s_in + p_in);
            float fc  = fg * cm;
            float gi  = ig * inn;
            float cmh = fc + gi * p_t1;
            cm        = fc + gi * p_t2;
            float og  = sigmoidf_(wc_og * cmh + s_og + p_og);
            hn        = og * tanhf(cmh);

            if (n < Nv - 1) {
                // Post our expect for the NEXT step's barrier now (same phase
                // the pushes credit), so the later wait is pure complete_tx.
                if (tid == 0) MBAR_ARRIVE_EXPECT_((q ^ 1) ? mb1 : mb0, 8192);
                // Push new h element into next-parity buffer of all 8 ranks.
                const uint32_t dloc = sbase + (uint32_t)(HB_OFF + (q ^ 1) * 2048 + kb * 256 + jg) * 4u;
                const uint32_t mloc = (q ^ 1) ? mb1 : mb0;
                #pragma unroll
                for (int rk = 0; rk < 8; rk++)
                    st_async_f32(dloc, mloc, (uint32_t)rk, hn);
            }
        }
        __syncthreads();   // red2 reuse + hbuf[q] reads done before next iter
    }

    CLUSTER_SYNC_();       // drain any in-flight DSMEM traffic before exit

    if (kb < 8) {
        out[(size_t)bg * 256 + jg]         = hn;
        out[32768 + (size_t)bg * 256 + jg] = cm;
    }
}

// ============================================================================
// Launch
// ============================================================================
extern "C" void kernel_launch(void* const* d_in, const int* in_sizes, int n_in,
                              void* d_out, int out_size)
{
    const float* x       = (const float*)d_in[0];
    const float* t       = (const float*)d_in[1];
    const float* fg_w_c  = (const float*)d_in[2];
    const float* fg_w_h  = (const float*)d_in[3];
    const float* fg_w_x  = (const float*)d_in[4];
    const float* fg_b    = (const float*)d_in[5];
    const float* ig_w_c  = (const float*)d_in[6];
    const float* ig_w_h  = (const float*)d_in[7];
    const float* ig_w_x  = (const float*)d_in[8];
    const float* ig_b    = (const float*)d_in[9];
    const float* in_w_h  = (const float*)d_in[10];
    const float* in_w_x  = (const float*)d_in[11];
    const float* in_b    = (const float*)d_in[12];
    const float* og_w_cn = (const float*)d_in[13];
    const float* og_w_h  = (const float*)d_in[14];
    const float* og_w_x  = (const float*)d_in[15];
    const float* og_b    = (const float*)d_in[16];
    const float* og_w_t  = (const float*)d_in[17];
    const float* tg1_w_x = (const float*)d_in[18];
    const float* tg1_w_t = (const float*)d_in[19];
    const float* tg1_b   = (const float*)d_in[20];
    const float* tg2_w_x = (const float*)d_in[21];
    const float* tg2_w_t = (const float*)d_in[22];
    const float* tg2_b   = (const float*)d_in[23];
    float* out = (float*)d_out;

    cudaFuncSetAttribute(precompute_kernel, cudaFuncAttributeMaxDynamicSharedMemorySize, 133120);
    cudaFuncSetAttribute(lstm_rec_kernel,   cudaFuncAttributeMaxDynamicSharedMemorySize, SMEM_REC_BYTES);

    dim3 gp(512, 12);
    precompute_kernel<<<gp, 256, 133120>>>(
        x, t,
        fg_w_x, fg_b, ig_w_x, ig_b, in_w_x, in_b,
        og_w_x, og_b, og_w_t,
        tg1_w_x, tg1_b, tg1_w_t,
        tg2_w_x, tg2_b, tg2_w_t);

    lstm_rec_kernel<<<128, REC_THREADS, SMEM_REC_BYTES>>>(
        fg_w_c, fg_w_h, ig_w_c, ig_w_h, in_w_h, og_w_cn, og_w_h, out);
}

// round 5
// speedup vs baseline: 1.0029x; 1.0029x over previous
#include <cuda_runtime.h>
#include <cstdint>

#define Bv 128
#define Nv 512
#define Xv 128
#define Hv 256
#define BN (Bv*Nv)           // 65536
#define GSZ (BN*Hv)          // 16777216 floats per gate buffer

// 6 precomputed gate-input buffers: 0=fg_x 1=ig_x 2=in_x 3=og_x 4=tm1 5=tm2
__device__ float g_pre[6][GSZ];

__device__ __forceinline__ float sigmoidf_(float v) { return 1.0f / (1.0f + __expf(-v)); }

// exp-based tanh: ~5 instr, rel err ~1e-6 (vs ~40-instr accurate tanhf).
// Args here are bounded (|x| << 44) so no overflow path needed.
__device__ __forceinline__ float tanh_fast_(float x) {
    float e = __expf(-2.0f * x);
    return __fdividef(1.0f - e, 1.0f + e);
}

__device__ __forceinline__ uint32_t smem_u32_(const void* p) {
    uint32_t a;
    asm("{ .reg .u64 t; cvta.to.shared.u64 t, %1; cvt.u32.u64 %0, t; }" : "=r"(a) : "l"(p));
    return a;
}

// ---- f32x2 packed-math helpers (sm_100a) ----
__device__ __forceinline__ unsigned long long pack2_(float a) {
    unsigned long long r;
    asm("mov.b64 %0, {%1, %1};" : "=l"(r) : "f"(a));
    return r;
}
__device__ __forceinline__ void ffma2_(unsigned long long& d, unsigned long long a, unsigned long long b) {
    asm("fma.rn.f32x2 %0, %1, %2, %0;" : "+l"(d) : "l"(a), "l"(b));
}
__device__ __forceinline__ float upadd_(unsigned long long v) {
    float lo, hi;
    asm("mov.b64 {%0, %1}, %2;" : "=f"(lo), "=f"(hi) : "l"(v));
    return lo + hi;
}
__device__ __forceinline__ float2 unpack2_(unsigned long long v) {
    float lo, hi;
    asm("mov.b64 {%0, %1}, %2;" : "=f"(lo), "=f"(hi) : "l"(v));
    return make_float2(lo, hi);
}

__device__ __forceinline__ void st_cluster_f32(uint32_t saddr, uint32_t rank, float v) {
    asm volatile(
        "{\n\t"
        ".reg .b32 ra;\n\t"
        "mapa.shared::cluster.u32 ra, %0, %1;\n\t"
        "st.shared::cluster.f32 [ra], %2;\n\t"
        "}"
        :: "r"(saddr), "r"(rank), "f"(v) : "memory");
}

#define CLUSTER_SYNC_() do { \
    asm volatile("barrier.cluster.arrive.aligned;" ::: "memory"); \
    asm volatile("barrier.cluster.wait.aligned;"   ::: "memory"); \
} while (0)

// ============================================================================
// Phase 1: precompute all input-dependent gate terms.
// grid (512 bn-tiles, 24 h-tiles of 64), block 256, 2 CTAs/SM (102400 B smem).
// Each block: 128 bn rows x 64 h cols of one gate. f32x2 inner loop.
// ============================================================================

#define XS_STRIDE 132
#define WS_STRIDE 68
#define PRE_SMEM_BYTES ((128 * XS_STRIDE + 128 * WS_STRIDE) * 4)   // 102400

__global__ void __launch_bounds__(256, 2) precompute_kernel(
    const float* __restrict__ x, const float* __restrict__ tvec,
    const float* __restrict__ fg_w_x, const float* __restrict__ fg_b,
    const float* __restrict__ ig_w_x, const float* __restrict__ ig_b,
    const float* __restrict__ in_w_x, const float* __restrict__ in_b,
    const float* __restrict__ og_w_x, const float* __restrict__ og_b, const float* __restrict__ og_w_t,
    const float* __restrict__ tg1_w_x, const float* __restrict__ tg1_b, const float* __restrict__ tg1_w_t,
    const float* __restrict__ tg2_w_x, const float* __restrict__ tg2_b, const float* __restrict__ tg2_w_t)
{
    extern __shared__ float sm[];
    float* xs = sm;                        // [128][132]
    float* ws = sm + 128 * XS_STRIDE;      // [128 k][68]  (transposed weights)

    const int tid  = threadIdx.x;
    const int bn0  = blockIdx.x * 128;
    const int ht   = blockIdx.y;
    const int gate = ht >> 2;
    const int hl0  = (ht & 3) * 64;

    const float* wptr; const float* bptr; const float* tptr = nullptr;
    switch (gate) {
        case 0:  wptr = fg_w_x;  bptr = fg_b;  break;
        case 1:  wptr = ig_w_x;  bptr = ig_b;  break;
        case 2:  wptr = in_w_x;  bptr = in_b;  break;
        case 3:  wptr = og_w_x;  bptr = og_b;  tptr = og_w_t;  break;
        case 4:  wptr = tg1_w_x; bptr = tg1_b; tptr = tg1_w_t; break;
        default: wptr = tg2_w_x; bptr = tg2_b; tptr = tg2_w_t; break;
    }

    // Load x tile [128 rows][128 k]
    for (int i = tid; i < 4096; i += 256) {
        int row = i >> 5, kq = i & 31;
        *(float4*)(xs + row * XS_STRIDE + kq * 4) =
            *(const float4*)(x + (size_t)(bn0 + row) * 128 + kq * 4);
    }
    // Load + transpose W tile (64 h rows) -> ws[k][h]
    for (int i = tid; i < 2048; i += 256) {
        int h = i >> 5, kq = i & 31;
        float4 v = *(const float4*)(wptr + (size_t)(hl0 + h) * 128 + kq * 4);
        ws[(kq * 4 + 0) * WS_STRIDE + h] = v.x;
        ws[(kq * 4 + 1) * WS_STRIDE + h] = v.y;
        ws[(kq * 4 + 2) * WS_STRIDE + h] = v.z;
        ws[(kq * 4 + 3) * WS_STRIDE + h] = v.w;
    }
    __syncthreads();

    const int trow = tid >> 3;   // 0..31 (4 rows each)
    const int tcol = tid & 7;    // 0..7  (8 cols each)

    unsigned long long acc2[4][4];
    #pragma unroll
    for (int i = 0; i < 4; i++) {
        #pragma unroll
        for (int q = 0; q < 4; q++) acc2[i][q] = 0ull;
    }

    #pragma unroll 2
    for (int k4 = 0; k4 < 32; ++k4) {
        float4 av[4];
        #pragma unroll
        for (int i = 0; i < 4; i++)
            av[i] = *(const float4*)(xs + (trow * 4 + i) * XS_STRIDE + k4 * 4);
        #pragma unroll
        for (int cc = 0; cc < 4; cc++) {
            const float* wr = ws + (k4 * 4 + cc) * WS_STRIDE + tcol * 8;
            ulonglong2 b01 = *(const ulonglong2*)(wr);
            ulonglong2 b23 = *(const ulonglong2*)(wr + 4);
            #pragma unroll
            for (int i = 0; i < 4; i++) {
                float a = (cc == 0) ? av[i].x : (cc == 1) ? av[i].y
                        : (cc == 2) ? av[i].z : av[i].w;
                unsigned long long aa = pack2_(a);
                ffma2_(acc2[i][0], aa, b01.x);
                ffma2_(acc2[i][1], aa, b01.y);
                ffma2_(acc2[i][2], aa, b23.x);
                ffma2_(acc2[i][3], aa, b23.y);
            }
        }
    }

    // Epilogue: biases, t-terms, activations; store to g_pre[gate]
    const int hgbase = hl0 + tcol * 8;
    float bias[8], tw[8];
    #pragma unroll
    for (int jj = 0; jj < 8; jj++) {
        bias[jj] = bptr[hgbase + jj];
        tw[jj]   = (tptr != nullptr) ? tptr[hgbase + jj] : 0.0f;
    }
    float* outg = &g_pre[gate][0];
    #pragma unroll
    for (int i = 0; i < 4; i++) {
        int row = bn0 + trow * 4 + i;
        float tv = (gate >= 3) ? tvec[row] : 0.0f;
        float oo[8];
        #pragma unroll
        for (int q = 0; q < 4; q++) {
            float2 u = unpack2_(acc2[i][q]);
            oo[2 * q]     = u.x;
            oo[2 * q + 1] = u.y;
        }
        float o[8];
        #pragma unroll
        for (int jj = 0; jj < 8; jj++) {
            float v;
            if (gate < 3)       v = oo[jj] + bias[jj];
            else if (gate == 3) v = oo[jj] + tw[jj] * tv + bias[jj];
            else                v = sigmoidf_(oo[jj] + tanhf(tw[jj] * tv) + bias[jj]);
            o[jj] = v;
        }
        float4* dst = (float4*)(outg + (size_t)row * 256 + hgbase);
        dst[0] = make_float4(o[0], o[1], o[2], o[3]);
        dst[1] = make_float4(o[4], o[5], o[6], o[7]);
    }
}

// ============================================================================
// Phase 2: recurrence. 16 clusters of 8 CTAs, 512 threads/CTA (16 warps).
// Cluster c: batch rows [8c, 8c+8). Rank r: H-slice [32r, 32r+32).
// Recurrent weights live in REGISTERS: thread (warp kb, lane j) holds
// W_g[r*32+j][kb*16 .. kb*16+16) for all 4 gates as 32 f32x2 pairs (64 regs).
// Per step: 4 register-passes over batch pairs -> smem k-reduction -> gates
// (warps 0-7) -> st.shared::cluster push of new h to all 8 ranks ->
// cluster.sync (doubles as block barrier). No weight LDS in the loop.
// dyn smem floats: hbuf 4096 | red2 16384  -> 81920 B.
// ============================================================================

#define REC_THREADS 512
#define RED_OFF 4096
#define SMEM_REC_BYTES ((4096 + 16384) * 4)

__global__ void __cluster_dims__(8, 1, 1) __launch_bounds__(REC_THREADS, 1) lstm_rec_kernel(
    const float* __restrict__ fg_w_c, const float* __restrict__ fg_w_h,
    const float* __restrict__ ig_w_c, const float* __restrict__ ig_w_h,
    const float* __restrict__ in_w_h,
    const float* __restrict__ og_w_cn, const float* __restrict__ og_w_h,
    float* __restrict__ out)
{
    extern __shared__ float sm[];
    float* hbuf = sm;                          // [2 parity][8 b][256 h]
    float2* red2 = (float2*)(sm + RED_OFF);    // [kc 16][s 8][gp 2][j 32]

    const int tid = threadIdx.x;
    const int r   = blockIdx.x & 7;
    const int grp = blockIdx.x >> 3;
    const int j   = tid & 31;          // output column within slice
    const int kb  = tid >> 5;          // warp id = k-chunk (16 k each)
    const int jg  = r * 32 + j;
    const int bg  = grp * 8 + kb;      // valid for kb<8 (epilogue role)

    const uint32_t sbase = smem_u32_(sm);

    // Weight registers: 8 f32x2 per gate (k pairs within this warp's chunk)
    unsigned long long wig[8], wfg[8], win[8], wog[8];
    {
        const int wo = jg * 256 + kb * 16;
        #pragma unroll
        for (int k2 = 0; k2 < 8; k2++) {
            wig[k2] = *(const unsigned long long*)(ig_w_h + wo + 2 * k2);
            wfg[k2] = *(const unsigned long long*)(fg_w_h + wo + 2 * k2);
            win[k2] = *(const unsigned long long*)(in_w_h + wo + 2 * k2);
            wog[k2] = *(const unsigned long long*)(og_w_h + wo + 2 * k2);
        }
    }

    for (int idx = tid; idx < 4096; idx += REC_THREADS) hbuf[idx] = 0.0f;

    const float wc_ig = ig_w_c[jg];
    const float wc_fg = fg_w_c[jg];
    const float wc_og = og_w_cn[jg];

    __syncthreads();
    CLUSTER_SYNC_();   // peers' zeroed buffers ready before any remote store

    float cm = 0.0f, hn = 0.0f;
    const size_t rowoff = (size_t)bg * Nv * 256 + jg;

    #pragma unroll 1
    for (int n = 0; n < Nv; ++n) {
        const int q = n & 1;

        // Prefetch streamed gate terms (owner warps only)
        float p_fg = 0.f, p_ig = 0.f, p_in = 0.f, p_og = 0.f, p_t1 = 0.f, p_t2 = 0.f;
        if (kb < 8) {
            const size_t off = rowoff + (size_t)n * 256;
            p_fg = __ldcs(&g_pre[0][off]);
            p_ig = __ldcs(&g_pre[1][off]);
            p_in = __ldcs(&g_pre[2][off]);
            p_og = __ldcs(&g_pre[3][off]);
            p_t1 = __ldcs(&g_pre[4][off]);
            p_t2 = __ldcs(&g_pre[5][off]);
        }

        // Matmul: 4 passes of 2 batch rows; weights from registers,
        // h via uniform (broadcast) LDS.128.
        const float* hc = hbuf + q * 2048 + kb * 16;
        #pragma unroll
        for (int p = 0; p < 4; ++p) {
            unsigned long long a00 = 0, a01 = 0, a02 = 0, a03 = 0;
            unsigned long long a10 = 0, a11 = 0, a12 = 0, a13 = 0;
            #pragma unroll
            for (int u = 0; u < 4; ++u) {
                ulonglong2 ha = *(const ulonglong2*)(hc + (2 * p)     * 256 + 4 * u);
                ulonglong2 hb = *(const ulonglong2*)(hc + (2 * p + 1) * 256 + 4 * u);
                ffma2_(a00, wig[2 * u], ha.x); ffma2_(a00, wig[2 * u + 1], ha.y);
                ffma2_(a01, wfg[2 * u], ha.x); ffma2_(a01, wfg[2 * u + 1], ha.y);
                ffma2_(a02, win[2 * u], ha.x); ffma2_(a02, win[2 * u + 1], ha.y);
                ffma2_(a03, wog[2 * u], ha.x); ffma2_(a03, wog[2 * u + 1], ha.y);
                ffma2_(a10, wig[2 * u], hb.x); ffma2_(a10, wig[2 * u + 1], hb.y);
                ffma2_(a11, wfg[2 * u], hb.x); ffma2_(a11, wfg[2 * u + 1], hb.y);
                ffma2_(a12, win[2 * u], hb.x); ffma2_(a12, win[2 * u + 1], hb.y);
                ffma2_(a13, wog[2 * u], hb.x); ffma2_(a13, wog[2 * u + 1], hb.y);
            }
            const int s0 = 2 * p, s1 = 2 * p + 1;
            red2[((kb * 8 + s0) * 2 + 0) * 32 + j] = make_float2(upadd_(a00), upadd_(a01));
            red2[((kb * 8 + s0) * 2 + 1) * 32 + j] = make_float2(upadd_(a02), upadd_(a03));
            red2[((kb * 8 + s1) * 2 + 0) * 32 + j] = make_float2(upadd_(a10), upadd_(a11));
            red2[((kb * 8 + s1) * 2 + 1) * 32 + j] = make_float2(upadd_(a12), upadd_(a13));
        }
        __syncthreads();

        if (kb < 8) {
            float s_ig = 0.f, s_fg = 0.f, s_in = 0.f, s_og = 0.f;
            #pragma unroll
            for (int kc = 0; kc < 16; kc++) {
                float2 v01 = red2[((kc * 8 + kb) * 2 + 0) * 32 + j];
                float2 v23 = red2[((kc * 8 + kb) * 2 + 1) * 32 + j];
                s_ig += v01.x; s_fg += v01.y; s_in += v23.x; s_og += v23.y;
            }

            float ig  = sigmoidf_(wc_ig * cm + s_ig + p_ig);
            float fg  = sigmoidf_(wc_fg * cm + s_fg + p_fg);
            float inn = tanh_fast_(s_in + p_in);
            float fc  = fg * cm;
            float gi  = ig * inn;
            float cmh = fc + gi * p_t1;
            cm        = fc + gi * p_t2;
            float og  = sigmoidf_(wc_og * cmh + s_og + p_og);
            hn        = og * tanh_fast_(cmh);

            if (n < Nv - 1) {
                // Push new h element into next-parity buffer of all 8 ranks.
                const uint32_t dst = sbase + (uint32_t)((q ^ 1) * 2048 + kb * 256 + jg) * 4u;
                #pragma unroll
                for (int rk = 0; rk < 8; rk++)
                    st_cluster_f32(dst, rk, hn);
            }
        }
        // Release/acquire remote stores; also serves as block barrier for red2.
        CLUSTER_SYNC_();
    }

    if (kb < 8) {
        out[(size_t)bg * 256 + jg]         = hn;
        out[32768 + (size_t)bg * 256 + jg] = cm;
    }
}

// ============================================================================
// Launch
// ============================================================================
extern "C" void kernel_launch(void* const* d_in, const int* in_sizes, int n_in,
                              void* d_out, int out_size)
{
    const float* x       = (const float*)d_in[0];
    const float* t       = (const float*)d_in[1];
    const float* fg_w_c  = (const float*)d_in[2];
    const float* fg_w_h  = (const float*)d_in[3];
    const float* fg_w_x  = (const float*)d_in[4];
    const float* fg_b    = (const float*)d_in[5];
    const float* ig_w_c  = (const float*)d_in[6];
    const float* ig_w_h  = (const float*)d_in[7];
    const float* ig_w_x  = (const float*)d_in[8];
    const float* ig_b    = (const float*)d_in[9];
    const float* in_w_h  = (const float*)d_in[10];
    const float* in_w_x  = (const float*)d_in[11];
    const float* in_b    = (const float*)d_in[12];
    const float* og_w_cn = (const float*)d_in[13];
    const float* og_w_h  = (const float*)d_in[14];
    const float* og_w_x  = (const float*)d_in[15];
    const float* og_b    = (const float*)d_in[16];
    const float* og_w_t  = (const float*)d_in[17];
    const float* tg1_w_x = (const float*)d_in[18];
    const float* tg1_w_t = (const float*)d_in[19];
    const float* tg1_b   = (const float*)d_in[20];
    const float* tg2_w_x = (const float*)d_in[21];
    const float* tg2_w_t = (const float*)d_in[22];
    const float* tg2_b   = (const float*)d_in[23];
    float* out = (float*)d_out;

    cudaFuncSetAttribute(precompute_kernel, cudaFuncAttributeMaxDynamicSharedMemorySize, PRE_SMEM_BYTES);
    cudaFuncSetAttribute(lstm_rec_kernel,   cudaFuncAttributeMaxDynamicSharedMemorySize, SMEM_REC_BYTES);

    dim3 gp(512, 24);
    precompute_kernel<<<gp, 256, PRE_SMEM_BYTES>>>(
        x, t,
        fg_w_x, fg_b, ig_w_x, ig_b, in_w_x, in_b,
        og_w_x, og_b, og_w_t,
        tg1_w_x, tg1_b, tg1_w_t,
        tg2_w_x, tg2_b, tg2_w_t);

    lstm_rec_kernel<<<128, REC_THREADS, SMEM_REC_BYTES>>>(
        fg_w_c, fg_w_h, ig_w_c, ig_w_h, in_w_h, og_w_cn, og_w_h, out);
}

// round 6
// speedup vs baseline: 1.0922x; 1.0891x over previous
#include <cuda_runtime.h>
#include <cstdint>

#define Bv 128
#define Nv 512
#define Xv 128
#define Hv 256
#define BN (Bv*Nv)           // 65536
#define GSZ (BN*Hv)          // 16777216 floats per gate buffer

// 6 precomputed gate-input buffers: 0=fg_x 1=ig_x 2=in_x 3=og_x 4=tm1 5=tm2
__device__ float g_pre[6][GSZ];

__device__ __forceinline__ float sigmoidf_(float v) { return 1.0f / (1.0f + __expf(-v)); }

// exp-based tanh: ~5 instr, rel err ~1e-6. Args bounded, no overflow path.
__device__ __forceinline__ float tanh_fast_(float x) {
    float e = __expf(-2.0f * x);
    return __fdividef(1.0f - e, 1.0f + e);
}

__device__ __forceinline__ uint32_t smem_u32_(const void* p) {
    uint32_t a;
    asm("{ .reg .u64 t; cvta.to.shared.u64 t, %1; cvt.u32.u64 %0, t; }" : "=r"(a) : "l"(p));
    return a;
}

// ---- f32x2 packed-math helpers (sm_100a) ----
__device__ __forceinline__ unsigned long long pack2_(float a) {
    unsigned long long r;
    asm("mov.b64 %0, {%1, %1};" : "=l"(r) : "f"(a));
    return r;
}
__device__ __forceinline__ void ffma2_(unsigned long long& d, unsigned long long a, unsigned long long b) {
    asm("fma.rn.f32x2 %0, %1, %2, %0;" : "+l"(d) : "l"(a), "l"(b));
}
__device__ __forceinline__ float upadd_(unsigned long long v) {
    float lo, hi;
    asm("mov.b64 {%0, %1}, %2;" : "=f"(lo), "=f"(hi) : "l"(v));
    return lo + hi;
}
__device__ __forceinline__ float2 unpack2_(unsigned long long v) {
    float lo, hi;
    asm("mov.b64 {%0, %1}, %2;" : "=f"(lo), "=f"(hi) : "l"(v));
    return make_float2(lo, hi);
}

// Bulk DSMEM copy: src (local smem, contiguous) -> rank rk's smem at same-offset
// dst, crediting rank rk's mbarrier with complete_tx bytes.
__device__ __forceinline__ void bulk_copy_rank_(uint32_t dst, uint32_t src,
                                                uint32_t mb, uint32_t rank,
                                                uint32_t bytes) {
    asm volatile(
        "{\n\t"
        ".reg .b32 rd, rm;\n\t"
        "mapa.shared::cluster.u32 rd, %0, %3;\n\t"
        "mapa.shared::cluster.u32 rm, %2, %3;\n\t"
        "cp.async.bulk.shared::cluster.shared::cta.mbarrier::complete_tx::bytes [rd], [%1], %4, [rm];\n\t"
        "}"
        :: "r"(dst), "r"(src), "r"(mb), "r"(rank), "r"(bytes) : "memory");
}

#define MBAR_INIT_(a, c) \
    asm volatile("mbarrier.init.shared.b64 [%0], %1;" :: "r"(a), "r"(c) : "memory")

#define MBAR_ARRIVE_EXPECT_(a, bytes) \
    asm volatile("mbarrier.arrive.expect_tx.shared.b64 _, [%0], %1;" \
                 :: "r"(a), "r"(bytes) : "memory")

#define FENCE_ASYNC_() asm volatile("fence.proxy.async.shared::cta;" ::: "memory")

__device__ __forceinline__ void mbar_wait_(uint32_t a, uint32_t parity) {
    asm volatile(
        "{\n\t"
        ".reg .pred P;\n\t"
        "WL_%=:\n\t"
        "mbarrier.try_wait.parity.acquire.cta.shared::cta.b64 P, [%0], %1, 0x989680;\n\t"
        "@P bra.uni WD_%=;\n\t"
        "bra.uni WL_%=;\n\t"
        "WD_%=:\n\t"
        "}"
        :: "r"(a), "r"(parity) : "memory");
}

#define CLUSTER_SYNC_() do { \
    asm volatile("barrier.cluster.arrive.aligned;" ::: "memory"); \
    asm volatile("barrier.cluster.wait.aligned;"   ::: "memory"); \
} while (0)

#define BAR_SYNC_(id, cnt) \
    asm volatile("bar.sync %0, %1;" :: "r"(id), "r"(cnt) : "memory")

// ============================================================================
// Phase 1: precompute all input-dependent gate terms. (as R5)
// grid (512 bn-tiles, 24 h-tiles of 64), block 256, 2 CTAs/SM.
// ============================================================================

#define XS_STRIDE 132
#define WS_STRIDE 68
#define PRE_SMEM_BYTES ((128 * XS_STRIDE + 128 * WS_STRIDE) * 4)   // 102400

__global__ void __launch_bounds__(256, 2) precompute_kernel(
    const float* __restrict__ x, const float* __restrict__ tvec,
    const float* __restrict__ fg_w_x, const float* __restrict__ fg_b,
    const float* __restrict__ ig_w_x, const float* __restrict__ ig_b,
    const float* __restrict__ in_w_x, const float* __restrict__ in_b,
    const float* __restrict__ og_w_x, const float* __restrict__ og_b, const float* __restrict__ og_w_t,
    const float* __restrict__ tg1_w_x, const float* __restrict__ tg1_b, const float* __restrict__ tg1_w_t,
    const float* __restrict__ tg2_w_x, const float* __restrict__ tg2_b, const float* __restrict__ tg2_w_t)
{
    extern __shared__ float sm[];
    float* xs = sm;                        // [128][132]
    float* ws = sm + 128 * XS_STRIDE;      // [128 k][68]

    const int tid  = threadIdx.x;
    const int bn0  = blockIdx.x * 128;
    const int ht   = blockIdx.y;
    const int gate = ht >> 2;
    const int hl0  = (ht & 3) * 64;

    const float* wptr; const float* bptr; const float* tptr = nullptr;
    switch (gate) {
        case 0:  wptr = fg_w_x;  bptr = fg_b;  break;
        case 1:  wptr = ig_w_x;  bptr = ig_b;  break;
        case 2:  wptr = in_w_x;  bptr = in_b;  break;
        case 3:  wptr = og_w_x;  bptr = og_b;  tptr = og_w_t;  break;
        case 4:  wptr = tg1_w_x; bptr = tg1_b; tptr = tg1_w_t; break;
        default: wptr = tg2_w_x; bptr = tg2_b; tptr = tg2_w_t; break;
    }

    for (int i = tid; i < 4096; i += 256) {
        int row = i >> 5, kq = i & 31;
        *(float4*)(xs + row * XS_STRIDE + kq * 4) =
            *(const float4*)(x + (size_t)(bn0 + row) * 128 + kq * 4);
    }
    for (int i = tid; i < 2048; i += 256) {
        int h = i >> 5, kq = i & 31;
        float4 v = *(const float4*)(wptr + (size_t)(hl0 + h) * 128 + kq * 4);
        ws[(kq * 4 + 0) * WS_STRIDE + h] = v.x;
        ws[(kq * 4 + 1) * WS_STRIDE + h] = v.y;
        ws[(kq * 4 + 2) * WS_STRIDE + h] = v.z;
        ws[(kq * 4 + 3) * WS_STRIDE + h] = v.w;
    }
    __syncthreads();

    const int trow = tid >> 3;   // 0..31
    const int tcol = tid & 7;    // 0..7

    unsigned long long acc2[4][4];
    #pragma unroll
    for (int i = 0; i < 4; i++) {
        #pragma unroll
        for (int q = 0; q < 4; q++) acc2[i][q] = 0ull;
    }

    #pragma unroll 2
    for (int k4 = 0; k4 < 32; ++k4) {
        float4 av[4];
        #pragma unroll
        for (int i = 0; i < 4; i++)
            av[i] = *(const float4*)(xs + (trow * 4 + i) * XS_STRIDE + k4 * 4);
        #pragma unroll
        for (int cc = 0; cc < 4; cc++) {
            const float* wr = ws + (k4 * 4 + cc) * WS_STRIDE + tcol * 8;
            ulonglong2 b01 = *(const ulonglong2*)(wr);
            ulonglong2 b23 = *(const ulonglong2*)(wr + 4);
            #pragma unroll
            for (int i = 0; i < 4; i++) {
                float a = (cc == 0) ? av[i].x : (cc == 1) ? av[i].y
                        : (cc == 2) ? av[i].z : av[i].w;
                unsigned long long aa = pack2_(a);
                ffma2_(acc2[i][0], aa, b01.x);
                ffma2_(acc2[i][1], aa, b01.y);
                ffma2_(acc2[i][2], aa, b23.x);
                ffma2_(acc2[i][3], aa, b23.y);
            }
        }
    }

    const int hgbase = hl0 + tcol * 8;
    float bias[8], tw[8];
    #pragma unroll
    for (int jj = 0; jj < 8; jj++) {
        bias[jj] = bptr[hgbase + jj];
        tw[jj]   = (tptr != nullptr) ? tptr[hgbase + jj] : 0.0f;
    }
    float* outg = &g_pre[gate][0];
    #pragma unroll
    for (int i = 0; i < 4; i++) {
        int row = bn0 + trow * 4 + i;
        float tv = (gate >= 3) ? tvec[row] : 0.0f;
        float oo[8];
        #pragma unroll
        for (int q = 0; q < 4; q++) {
            float2 u = unpack2_(acc2[i][q]);
            oo[2 * q]     = u.x;
            oo[2 * q + 1] = u.y;
        }
        float o[8];
        #pragma unroll
        for (int jj = 0; jj < 8; jj++) {
            float v;
            if (gate < 3)       v = oo[jj] + bias[jj];
            else if (gate == 3) v = oo[jj] + tw[jj] * tv + bias[jj];
            else                v = sigmoidf_(oo[jj] + tanhf(tw[jj] * tv) + bias[jj]);
            o[jj] = v;
        }
        float4* dst = (float4*)(outg + (size_t)row * 256 + hgbase);
        dst[0] = make_float4(o[0], o[1], o[2], o[3]);
        dst[1] = make_float4(o[4], o[5], o[6], o[7]);
    }
}

// ============================================================================
// Phase 2: recurrence, latency-hidden.
// 16 clusters x 8 CTAs x 512 threads. Cluster c: rows [8c,8c+8), split into
// group A = rows 0-3, group B = rows 4-7 of the cluster, processed back-to-back
// each iteration so A's h-exchange overlaps B's compute and vice versa.
// Weights in registers (k-chunk 16/warp, 64 regs). h exchanged with 8x 512B
// cp.async.bulk DSMEM copies per group-step, mbarrier complete_tx signaling.
// ============================================================================

#define REC_THREADS 512
// smem float offsets
#define HBA 0                 // hbufA [2 par][8 r][4 b][32 j]
#define HBB 2048              // hbufB same
#define STA 4096              // stgA  [2 par][128]
#define STB 4352              // stgB
#define RDA 4608              // redA float2 [16 kc][4 b][2 gp][32 j]
#define RDB 12800             // redB
#define MBARo 20992           // 4 x u64
#define SMEM_REC_BYTES ((21008) * 4)

__global__ void __cluster_dims__(8, 1, 1) __launch_bounds__(REC_THREADS, 1) lstm_rec_kernel(
    const float* __restrict__ fg_w_c, const float* __restrict__ fg_w_h,
    const float* __restrict__ ig_w_c, const float* __restrict__ ig_w_h,
    const float* __restrict__ in_w_h,
    const float* __restrict__ og_w_cn, const float* __restrict__ og_w_h,
    float* __restrict__ out)
{
    extern __shared__ float sm[];
    const int tid = threadIdx.x;
    const int r   = blockIdx.x & 7;
    const int grp = blockIdx.x >> 3;
    const int j   = tid & 31;
    const int w   = tid >> 5;          // warp id = k-chunk (16 k)
    const int jg  = r * 32 + j;

    const uint32_t sbase = smem_u32_(sm);
    const uint32_t mbA0 = sbase + MBARo * 4;
    const uint32_t mbA1 = mbA0 + 8;
    const uint32_t mbB0 = mbA0 + 16;
    const uint32_t mbB1 = mbA0 + 24;

    // Weight registers: k-chunk [16w, 16w+16), 8 f32x2 per gate.
    unsigned long long wig[8], wfg[8], win[8], wog[8];
    {
        const int wo = jg * 256 + w * 16;
        #pragma unroll
        for (int k2 = 0; k2 < 8; k2++) {
            wig[k2] = *(const unsigned long long*)(ig_w_h + wo + 2 * k2);
            wfg[k2] = *(const unsigned long long*)(fg_w_h + wo + 2 * k2);
            win[k2] = *(const unsigned long long*)(in_w_h + wo + 2 * k2);
            wog[k2] = *(const unsigned long long*)(og_w_h + wo + 2 * k2);
        }
    }

    // Zero both h buffers (all parities)
    for (int idx = tid; idx < 4096; idx += REC_THREADS) sm[HBA + idx] = 0.0f;

    if (tid == 0) {
        MBAR_INIT_(mbA0, 1); MBAR_INIT_(mbA1, 1);
        MBAR_INIT_(mbB0, 1); MBAR_INIT_(mbB1, 1);
        // First-phase expects (credits arrive only after the cluster sync).
        MBAR_ARRIVE_EXPECT_(mbA0, 4096); MBAR_ARRIVE_EXPECT_(mbA1, 4096);
        MBAR_ARRIVE_EXPECT_(mbB0, 4096); MBAR_ARRIVE_EXPECT_(mbB1, 4096);
    }

    const float wc_ig = ig_w_c[jg];
    const float wc_fg = fg_w_c[jg];
    const float wc_og = og_w_cn[jg];

    __syncthreads();
    CLUSTER_SYNC_();   // mbarriers + zeroed buffers visible before any copy

    const int ownA = (w < 4);
    const int ownB = (w >= 4 && w < 8);
    const int bO   = ownA ? w : (w - 4);             // owner's batch row in group
    const int bgA  = grp * 8 + w;                    // ownA
    const int bgB  = grp * 8 + 4 + (w - 4);          // ownB
    const size_t rowoffA = (size_t)bgA * Nv * 256 + jg;
    const size_t rowoffB = (size_t)bgB * Nv * 256 + jg;

    float cmv = 0.0f, hnv = 0.0f;   // owner-thread recurrent state (A or B)
    uint32_t phA0 = 0, phA1 = 0, phB0 = 0, phB1 = 0;

    // k-chunk geometry for h loads (rank-major hbuf)
    const int hoff = ((w >> 1) & 7) * 128 + (w & 1) * 16;

    #pragma unroll 1
    for (int n = 0; n < Nv; ++n) {
        const int q = n & 1;

        // ================= group A =================
        if (n != 0) {
            const uint32_t mb = q ? mbA1 : mbA0;
            mbar_wait_(mb, q ? phA1 : phA0);
            if (q) phA1 ^= 1; else phA0 ^= 1;
            if (tid == 0) MBAR_ARRIVE_EXPECT_(mb, 4096);
        }
        float p0 = 0.f, p1 = 0.f, p2 = 0.f, p3 = 0.f, p4 = 0.f, p5 = 0.f;
        if (ownA) {
            const size_t off = rowoffA + (size_t)n * 256;
            p0 = __ldcs(&g_pre[0][off]); p1 = __ldcs(&g_pre[1][off]);
            p2 = __ldcs(&g_pre[2][off]); p3 = __ldcs(&g_pre[3][off]);
            p4 = __ldcs(&g_pre[4][off]); p5 = __ldcs(&g_pre[5][off]);
        }
        {
            const float* hc = sm + HBA + q * 1024 + hoff;
            float2* red = (float2*)(sm + RDA);
            #pragma unroll
            for (int p = 0; p < 2; ++p) {
                const int b0 = 2 * p, b1 = 2 * p + 1;
                unsigned long long a00 = 0, a01 = 0, a02 = 0, a03 = 0;
                unsigned long long a10 = 0, a11 = 0, a12 = 0, a13 = 0;
                #pragma unroll
                for (int u = 0; u < 4; ++u) {
                    ulonglong2 ha = *(const ulonglong2*)(hc + b0 * 32 + 4 * u);
                    ulonglong2 hb = *(const ulonglong2*)(hc + b1 * 32 + 4 * u);
                    ffma2_(a00, wig[2*u], ha.x); ffma2_(a00, wig[2*u+1], ha.y);
                    ffma2_(a01, wfg[2*u], ha.x); ffma2_(a01, wfg[2*u+1], ha.y);
                    ffma2_(a02, win[2*u], ha.x); ffma2_(a02, win[2*u+1], ha.y);
                    ffma2_(a03, wog[2*u], ha.x); ffma2_(a03, wog[2*u+1], ha.y);
                    ffma2_(a10, wig[2*u], hb.x); ffma2_(a10, wig[2*u+1], hb.y);
                    ffma2_(a11, wfg[2*u], hb.x); ffma2_(a11, wfg[2*u+1], hb.y);
                    ffma2_(a12, win[2*u], hb.x); ffma2_(a12, win[2*u+1], hb.y);
                    ffma2_(a13, wog[2*u], hb.x); ffma2_(a13, wog[2*u+1], hb.y);
                }
                red[((w * 4 + b0) * 2 + 0) * 32 + j] = make_float2(upadd_(a00), upadd_(a01));
                red[((w * 4 + b0) * 2 + 1) * 32 + j] = make_float2(upadd_(a02), upadd_(a03));
                red[((w * 4 + b1) * 2 + 0) * 32 + j] = make_float2(upadd_(a10), upadd_(a11));
                red[((w * 4 + b1) * 2 + 1) * 32 + j] = make_float2(upadd_(a12), upadd_(a13));
            }
        }
        __syncthreads();
        if (ownA) {
            const float2* red = (const float2*)(sm + RDA);
            float s_ig = 0.f, s_fg = 0.f, s_in = 0.f, s_og = 0.f;
            #pragma unroll
            for (int kc = 0; kc < 16; kc++) {
                float2 v01 = red[((kc * 4 + bO) * 2 + 0) * 32 + j];
                float2 v23 = red[((kc * 4 + bO) * 2 + 1) * 32 + j];
                s_ig += v01.x; s_fg += v01.y; s_in += v23.x; s_og += v23.y;
            }
            float ig  = sigmoidf_(wc_ig * cmv + s_ig + p1);
            float fg  = sigmoidf_(wc_fg * cmv + s_fg + p0);
            float inn = tanh_fast_(s_in + p2);
            float fc  = fg * cmv;
            float gi  = ig * inn;
            float cmh = fc + gi * p4;
            cmv       = fc + gi * p5;
            float og  = sigmoidf_(wc_og * cmh + s_og + p3);
            hnv       = og * tanh_fast_(cmh);
            if (n < Nv - 1) sm[STA + (q ^ 1) * 128 + bO * 32 + j] = hnv;
            BAR_SYNC_(3, 128);
            if (tid < 8 && n < Nv - 1) {
                FENCE_ASYNC_();
                bulk_copy_rank_(sbase + (HBA + (q ^ 1) * 1024 + r * 128) * 4,
                                sbase + (STA + (q ^ 1) * 128) * 4,
                                (q ^ 1) ? mbA1 : mbA0, (uint32_t)tid, 512);
            }
        }

        // ================= group B =================
        if (n != 0) {
            const uint32_t mb = q ? mbB1 : mbB0;
            mbar_wait_(mb, q ? phB1 : phB0);
            if (q) phB1 ^= 1; else phB0 ^= 1;
            if (tid == 128) MBAR_ARRIVE_EXPECT_(mb, 4096);
        }
        if (ownB) {
            const size_t off = rowoffB + (size_t)n * 256;
            p0 = __ldcs(&g_pre[0][off]); p1 = __ldcs(&g_pre[1][off]);
            p2 = __ldcs(&g_pre[2][off]); p3 = __ldcs(&g_pre[3][off]);
            p4 = __ldcs(&g_pre[4][off]); p5 = __ldcs(&g_pre[5][off]);
        }
        {
            const float* hc = sm + HBB + q * 1024 + hoff;
            float2* red = (float2*)(sm + RDB);
            #pragma unroll
            for (int p = 0; p < 2; ++p) {
                const int b0 = 2 * p, b1 = 2 * p + 1;
                unsigned long long a00 = 0, a01 = 0, a02 = 0, a03 = 0;
                unsigned long long a10 = 0, a11 = 0, a12 = 0, a13 = 0;
                #pragma unroll
                for (int u = 0; u < 4; ++u) {
                    ulonglong2 ha = *(const ulonglong2*)(hc + b0 * 32 + 4 * u);
                    ulonglong2 hb = *(const ulonglong2*)(hc + b1 * 32 + 4 * u);
                    ffma2_(a00, wig[2*u], ha.x); ffma2_(a00, wig[2*u+1], ha.y);
                    ffma2_(a01, wfg[2*u], ha.x); ffma2_(a01, wfg[2*u+1], ha.y);
                    ffma2_(a02, win[2*u], ha.x); ffma2_(a02, win[2*u+1], ha.y);
                    ffma2_(a03, wog[2*u], ha.x); ffma2_(a03, wog[2*u+1], ha.y);
                    ffma2_(a10, wig[2*u], hb.x); ffma2_(a10, wig[2*u+1], hb.y);
                    ffma2_(a11, wfg[2*u], hb.x); ffma2_(a11, wfg[2*u+1], hb.y);
                    ffma2_(a12, win[2*u], hb.x); ffma2_(a12, win[2*u+1], hb.y);
                    ffma2_(a13, wog[2*u], hb.x); ffma2_(a13, wog[2*u+1], hb.y);
                }
                red[((w * 4 + b0) * 2 + 0) * 32 + j] = make_float2(upadd_(a00), upadd_(a01));
                red[((w * 4 + b0) * 2 + 1) * 32 + j] = make_float2(upadd_(a02), upadd_(a03));
                red[((w * 4 + b1) * 2 + 0) * 32 + j] = make_float2(upadd_(a10), upadd_(a11));
                red[((w * 4 + b1) * 2 + 1) * 32 + j] = make_float2(upadd_(a12), upadd_(a13));
            }
        }
        __syncthreads();
        if (ownB) {
            const float2* red = (const float2*)(sm + RDB);
            float s_ig = 0.f, s_fg = 0.f, s_in = 0.f, s_og = 0.f;
            #pragma unroll
            for (int kc = 0; kc < 16; kc++) {
                float2 v01 = red[((kc * 4 + bO) * 2 + 0) * 32 + j];
                float2 v23 = red[((kc * 4 + bO) * 2 + 1) * 32 + j];
                s_ig += v01.x; s_fg += v01.y; s_in += v23.x; s_og += v23.y;
            }
            float ig  = sigmoidf_(wc_ig * cmv + s_ig + p1);
            float fg  = sigmoidf_(wc_fg * cmv + s_fg + p0);
            float inn = tanh_fast_(s_in + p2);
            float fc  = fg * cmv;
            float gi  = ig * inn;
            float cmh = fc + gi * p4;
            cmv       = fc + gi * p5;
            float og  = sigmoidf_(wc_og * cmh + s_og + p3);
            hnv       = og * tanh_fast_(cmh);
            if (n < Nv - 1) sm[STB + (q ^ 1) * 128 + bO * 32 + j] = hnv;
            BAR_SYNC_(4, 128);
            if (tid >= 128 && tid < 136 && n < Nv - 1) {
                FENCE_ASYNC_();
                bulk_copy_rank_(sbase + (HBB + (q ^ 1) * 1024 + r * 128) * 4,
                                sbase + (STB + (q ^ 1) * 128) * 4,
                                (q ^ 1) ? mbB1 : mbB0, (uint32_t)(tid - 128), 512);
            }
        }
    }

    CLUSTER_SYNC_();   // keep cluster resident until all copies consumed

    if (ownA) {
        out[(size_t)bgA * 256 + jg]         = hnv;
        out[32768 + (size_t)bgA * 256 + jg] = cmv;
    } else if (ownB) {
        out[(size_t)bgB * 256 + jg]         = hnv;
        out[32768 + (size_t)bgB * 256 + jg] = cmv;
    }
}

// ============================================================================
// Launch
// ============================================================================
extern "C" void kernel_launch(void* const* d_in, const int* in_sizes, int n_in,
                              void* d_out, int out_size)
{
    const float* x       = (const float*)d_in[0];
    const float* t       = (const float*)d_in[1];
    const float* fg_w_c  = (const float*)d_in[2];
    const float* fg_w_h  = (const float*)d_in[3];
    const float* fg_w_x  = (const float*)d_in[4];
    const float* fg_b    = (const float*)d_in[5];
    const float* ig_w_c  = (const float*)d_in[6];
    const float* ig_w_h  = (const float*)d_in[7];
    const float* ig_w_x  = (const float*)d_in[8];
    const float* ig_b    = (const float*)d_in[9];
    const float* in_w_h  = (const float*)d_in[10];
    const float* in_w_x  = (const float*)d_in[11];
    const float* in_b    = (const float*)d_in[12];
    const float* og_w_cn = (const float*)d_in[13];
    const float* og_w_h  = (const float*)d_in[14];
    const float* og_w_x  = (const float*)d_in[15];
    const float* og_b    = (const float*)d_in[16];
    const float* og_w_t  = (const float*)d_in[17];
    const float* tg1_w_x = (const float*)d_in[18];
    const float* tg1_w_t = (const float*)d_in[19];
    const float* tg1_b   = (const float*)d_in[20];
    const float* tg2_w_x = (const float*)d_in[21];
    const float* tg2_w_t = (const float*)d_in[22];
    const float* tg2_b   = (const float*)d_in[23];
    float* out = (float*)d_out;

    cudaFuncSetAttribute(precompute_kernel, cudaFuncAttributeMaxDynamicSharedMemorySize, PRE_SMEM_BYTES);
    cudaFuncSetAttribute(lstm_rec_kernel,   cudaFuncAttributeMaxDynamicSharedMemorySize, SMEM_REC_BYTES);

    dim3 gp(512, 24);
    precompute_kernel<<<gp, 256, PRE_SMEM_BYTES>>>(
        x, t,
        fg_w_x, fg_b, ig_w_x, ig_b, in_w_x, in_b,
        og_w_x, og_b, og_w_t,
        tg1_w_x, tg1_b, tg1_w_t,
        tg2_w_x, tg2_b, tg2_w_t);

    lstm_rec_kernel<<<128, REC_THREADS, SMEM_REC_BYTES>>>(
        fg_w_c, fg_w_h, ig_w_c, ig_w_h, in_w_h, og_w_cn, og_w_h, out);
}